// round 10
// baseline (speedup 1.0000x reference)
#include <cuda_runtime.h>
#include <math.h>

#define BSZ  32
#define SEQ  4096
#define ENC  512
#define TMAX 64

// Scratch: per-(b,t) logit-difference contributions. __device__ globals (no alloc).
__device__ float g_dl[BSZ * TMAX];
__device__ float g_dr[BSZ * TMAX];

// Kernel 1: gather + two weight-difference dot products per (b,t).
// 256 blocks x 256 threads; each warp owns one (b,t) row (2048 rows total).
__global__ void __launch_bounds__(256) proj_kernel(const float* __restrict__ enc,
                                                   const int*   __restrict__ ids,
                                                   const float* __restrict__ W) {
    __shared__ float wdl[ENC];
    __shared__ float wdr[ENC];
    const int tid = threadIdx.x;

    // Stage weight-difference vectors once per block.
    // W layout (2, 2*ENC) row-major: W0 = W[0..1024), W1 = W[1024..2048).
    for (int i = tid; i < ENC; i += 256) {
        wdl[i] = W[1024 + i]       - W[i];          // Wl1 - Wl0
        wdr[i] = W[1536 + i]       - W[512 + i];    // Wr1 - Wr0
    }
    __syncthreads();

    const int warp = tid >> 5;
    const int lane = tid & 31;
    const int row  = blockIdx.x * 8 + warp;         // 0..2047  == b*64 + t
    const int b    = row >> 6;
    const int id   = ids[row];

    const float4* __restrict__ src = (const float4*)(enc + ((size_t)b * SEQ + id) * ENC);
    const float4* __restrict__ l4  = (const float4*)wdl;
    const float4* __restrict__ r4  = (const float4*)wdr;

    float dl = 0.f, dr = 0.f;
#pragma unroll
    for (int i = 0; i < 4; i++) {
        const int c = lane + i * 32;                // 128 float4 per row
        const float4 x  = src[c];
        const float4 a  = l4[c];
        const float4 bb = r4[c];
        dl = fmaf(x.x, a.x,  fmaf(x.y, a.y,  fmaf(x.z, a.z,  fmaf(x.w, a.w,  dl))));
        dr = fmaf(x.x, bb.x, fmaf(x.y, bb.y, fmaf(x.z, bb.z, fmaf(x.w, bb.w, dr))));
    }
#pragma unroll
    for (int o = 16; o; o >>= 1) {
        dl += __shfl_xor_sync(0xffffffffu, dl, o);
        dr += __shfl_xor_sync(0xffffffffu, dr, o);
    }
    if (lane == 0) {
        g_dl[row] = dl;
        g_dr[row] = dr;
    }
}

// Kernel 2: pairwise masked CE + reduction. Single CTA (work is tiny).
__global__ void __launch_bounds__(1024) loss_kernel(const int*   __restrict__ tl,
                                                    const float* __restrict__ bias,
                                                    float*       __restrict__ out) {
    __shared__ float sdl[BSZ * TMAX];
    __shared__ float sdr[BSZ * TMAX];
    __shared__ int   slen[BSZ];
    __shared__ float swsum[32];
    __shared__ int   swcnt[32];

    const int tid = threadIdx.x;
    for (int i = tid; i < BSZ * TMAX; i += 1024) {
        sdl[i] = g_dl[i];
        sdr[i] = g_dr[i];
    }
    if (tid < BSZ) slen[tid] = tl[tid];
    __syncthreads();

    const float db = bias[1] - bias[0];

    float sum = 0.f;
    int   cnt = 0;
    // 32*64*64 = 131072 pairs, 128 per thread.
    for (int p = tid; p < BSZ * TMAX * TMAX; p += 1024) {
        const int b = p >> 12;
        const int j = (p >> 6) & 63;
        const int k = p & 63;
        if (k < j && j < slen[b]) {
            const float d = sdl[b * 64 + j] + sdr[b * 64 + k] + db;
            const float x = (k == j - 1) ? -d : d;       // label -> -logp1, else -logp0
            // numerically stable softplus(x) = max(x,0) + log1p(exp(-|x|))
            const float ce = fmaxf(x, 0.f) + log1pf(expf(-fabsf(x)));
            sum += ce;
            cnt += 1;
        }
    }

#pragma unroll
    for (int o = 16; o; o >>= 1) {
        sum += __shfl_xor_sync(0xffffffffu, sum, o);
        cnt += __shfl_xor_sync(0xffffffffu, cnt, o);
    }
    const int warp = tid >> 5;
    const int lane = tid & 31;
    if (lane == 0) { swsum[warp] = sum; swcnt[warp] = cnt; }
    __syncthreads();
    if (warp == 0) {
        sum = (lane < 32) ? swsum[lane] : 0.f;
        cnt = (lane < 32) ? swcnt[lane] : 0;
#pragma unroll
        for (int o = 16; o; o >>= 1) {
            sum += __shfl_xor_sync(0xffffffffu, sum, o);
            cnt += __shfl_xor_sync(0xffffffffu, cnt, o);
        }
        if (lane == 0) out[0] = sum / (float)max(cnt, 1);
    }
}

extern "C" void kernel_launch(void* const* d_in, const int* in_sizes, int n_in,
                              void* d_out, int out_size) {
    // metadata order: encoder_output, his_turn_end_ids, turn_lengths, W, b
    const float* enc  = (const float*)d_in[0];
    const int*   ids  = (const int*)  d_in[1];
    const int*   tl   = (const int*)  d_in[2];
    const float* W    = (const float*)d_in[3];
    const float* bias = (const float*)d_in[4];
    float*       out  = (float*)d_out;

    proj_kernel<<<256, 256>>>(enc, ids, W);
    loss_kernel<<<1, 1024>>>(tl, bias, out);
}

// round 11
// speedup vs baseline: 2.9286x; 2.9286x over previous
#include <cuda_runtime.h>
#include <math.h>

#define BSZ  32
#define SEQ  4096
#define ENC  512
#define TMAX 64

// Scratch: per-(b,t) logit-difference contributions + cross-block reduction.
// __device__ globals (allocation-guard safe). g_sum/g_done are reset by the
// finalizing block each launch, so graph replays stay deterministic.
__device__ float    g_dl[BSZ * TMAX];
__device__ float    g_dr[BSZ * TMAX];
__device__ float    g_sum;        // zero-init at load; reset each launch
__device__ unsigned g_done;       // zero-init at load; reset each launch

// Kernel 1: gather + two weight-difference dot products per (b,t).
// 256 blocks x 256 threads; each warp owns one (b,t) row (2048 rows total).
__global__ void __launch_bounds__(256) proj_kernel(const float* __restrict__ enc,
                                                   const int*   __restrict__ ids,
                                                   const float* __restrict__ W) {
    __shared__ float wdl[ENC];
    __shared__ float wdr[ENC];
    const int tid = threadIdx.x;

    // Stage weight-difference vectors once per block.
    // W layout (2, 2*ENC) row-major: W0 = W[0..1024), W1 = W[1024..2048).
    for (int i = tid; i < ENC; i += 256) {
        wdl[i] = W[1024 + i] - W[i];          // Wl1 - Wl0
        wdr[i] = W[1536 + i] - W[512 + i];    // Wr1 - Wr0
    }
    __syncthreads();

    const int warp = tid >> 5;
    const int lane = tid & 31;
    const int row  = blockIdx.x * 8 + warp;   // 0..2047 == b*64 + t
    const int b    = row >> 6;
    const int id   = ids[row];

    const float4* __restrict__ src = (const float4*)(enc + ((size_t)b * SEQ + id) * ENC);
    const float4* __restrict__ l4  = (const float4*)wdl;
    const float4* __restrict__ r4  = (const float4*)wdr;

    float dl = 0.f, dr = 0.f;
#pragma unroll
    for (int i = 0; i < 4; i++) {
        const int c = lane + i * 32;          // 128 float4 per row
        const float4 x  = src[c];
        const float4 a  = l4[c];
        const float4 bb = r4[c];
        dl = fmaf(x.x, a.x,  fmaf(x.y, a.y,  fmaf(x.z, a.z,  fmaf(x.w, a.w,  dl))));
        dr = fmaf(x.x, bb.x, fmaf(x.y, bb.y, fmaf(x.z, bb.z, fmaf(x.w, bb.w, dr))));
    }
#pragma unroll
    for (int o = 16; o; o >>= 1) {
        dl += __shfl_xor_sync(0xffffffffu, dl, o);
        dr += __shfl_xor_sync(0xffffffffu, dr, o);
    }
    if (lane == 0) {
        g_dl[row] = dl;
        g_dr[row] = dr;
    }
}

// Kernel 2: pairwise masked CE, one CTA per batch element (32 CTAs).
// Uses softplus(-d) = softplus(d) - d to kill the label select, and
// fast-math __expf/__logf (2 MUFU ops) instead of software log1pf.
__global__ void __launch_bounds__(512) loss_kernel(const int*   __restrict__ tl,
                                                   const float* __restrict__ bias,
                                                   float*       __restrict__ out) {
    __shared__ float sdl[TMAX];
    __shared__ float sdr[TMAX];
    __shared__ float wsum[16];
    __shared__ int   sT;

    const int b   = blockIdx.x;
    const int tid = threadIdx.x;

    if (tid < TMAX) {
        sdl[tid] = g_dl[b * TMAX + tid];
        sdr[tid] = g_dr[b * TMAX + tid];
    }
    if (tid == 0) sT = tl[b];
    __syncthreads();

    const int   T  = sT;
    const float db = bias[1] - bias[0];

    float sum = 0.f;
    // Flat over 64x64 = 4096 pairs, 8 per thread; valid: k < j < T.
#pragma unroll
    for (int p = tid; p < TMAX * TMAX; p += 512) {
        const int j = p >> 6;
        const int k = p & 63;
        if (k < j && j < T) {
            const float d  = sdl[j] + sdr[k] + db;
            float sp = fmaxf(d, 0.f) + __logf(1.f + __expf(-fabsf(d)));
            if (k == j - 1) sp -= d;          // label pair: softplus(-d) = softplus(d)-d
            sum += sp;
        }
    }

    // Block reduce.
#pragma unroll
    for (int o = 16; o; o >>= 1) sum += __shfl_xor_sync(0xffffffffu, sum, o);
    const int warp = tid >> 5;
    const int lane = tid & 31;
    if (lane == 0) wsum[warp] = sum;
    __syncthreads();
    if (warp == 0) {
        sum = (lane < 16) ? wsum[lane] : 0.f;
#pragma unroll
        for (int o = 8; o; o >>= 1) sum += __shfl_xor_sync(0xffffffffu, sum, o);

        if (lane == 0) {
            atomicAdd(&g_sum, sum);
            __threadfence();
            const unsigned ticket = atomicAdd(&g_done, 1u);
            if (ticket == BSZ - 1) {
                // All 32 partials are in. Closed-form valid-pair count:
                // per batch, pairs (j,k): k<j<T  ->  T*(T-1)/2.
                long long cnt = 0;
                for (int i = 0; i < BSZ; i++) {
                    const long long L = tl[i];
                    cnt += L * (L - 1) / 2;
                }
                if (cnt < 1) cnt = 1;
                const float s = atomicAdd(&g_sum, 0.f);   // coherent L2 read
                out[0] = s / (float)cnt;
                // Reset scratch for the next graph replay.
                g_sum  = 0.f;
                g_done = 0u;
            }
        }
    }
}

extern "C" void kernel_launch(void* const* d_in, const int* in_sizes, int n_in,
                              void* d_out, int out_size) {
    // metadata order: encoder_output, his_turn_end_ids, turn_lengths, W, b
    const float* enc  = (const float*)d_in[0];
    const int*   ids  = (const int*)  d_in[1];
    const int*   tl   = (const int*)  d_in[2];
    const float* W    = (const float*)d_in[3];
    const float* bias = (const float*)d_in[4];
    float*       out  = (float*)d_out;

    proj_kernel<<<256, 256>>>(enc, ids, W);
    loss_kernel<<<BSZ, 512>>>(tl, bias, out);
}

// round 12
// speedup vs baseline: 2.9373x; 1.0030x over previous
#include <cuda_runtime.h>
#include <math.h>

#define BSZ  32
#define SEQ  4096
#define ENC  512
#define TMAX 64

// Scratch (__device__ globals — allocation-guard safe). All counters are
// reset by their unique consumer within the same launch, so graph replays
// are deterministic.
__device__ float    g_dl[BSZ * TMAX];
__device__ float    g_dr[BSZ * TMAX];
__device__ int      g_barr[BSZ];     // per-batch arrival counters (8 CTAs each)
__device__ float    g_sum;           // global CE sum
__device__ int      g_cnt;           // global valid-pair count
__device__ unsigned g_done;          // batches finished

// Single fused kernel: gather+projection, per-batch software barrier,
// per-batch pairwise CE, global reduction. 256 CTAs x 256 threads.
// CTA c owns rows 8c..8c+7; CTAs 8b..8b+7 together cover batch b.
__global__ void __launch_bounds__(256) fused_kernel(const float* __restrict__ enc,
                                                    const int*   __restrict__ ids,
                                                    const int*   __restrict__ tl,
                                                    const float* __restrict__ bias,
                                                    float*       __restrict__ out) {
    __shared__ float wdl[ENC];
    __shared__ float wdr[ENC];
    __shared__ float sdl[TMAX];
    __shared__ float sdr[TMAX];
    __shared__ float wsum[8];
    __shared__ int   s_ticket;

    const int tid  = threadIdx.x;
    const int warp = tid >> 5;
    const int lane = tid & 31;

    // ---- Phase 1: stage weight-difference vectors ----
    // W layout (2, 2*ENC) row-major: W0 = W[0..1024), W1 = W[1024..2048).
    const float* __restrict__ W = bias - 0;  // placeholder, replaced below
    (void)W;

    // ---- Phase 1 proper: gather + two dots per (b,t) row ----
    const int row = blockIdx.x * 8 + warp;   // 0..2047 == b*64 + t
    const int b   = blockIdx.x >> 3;         // batch this CTA belongs to

    // Stage wdl/wdr (weight diffs) — passed via enc? No: W comes in as a
    // separate pointer; see kernel_launch signature below.
    extern __shared__ float dummy_unused[];  // (not used; static smem only)
    (void)dummy_unused;

    // NOTE: actual W pointer is the 5th param; declared below in real signature.
    // (This block intentionally left to the real implementation.)
    out = out; // no-op
    // -- real implementation continues in fused_kernel2 --
}

// Real fused kernel (clean signature).
__global__ void __launch_bounds__(256) fused(const float* __restrict__ enc,
                                             const int*   __restrict__ ids,
                                             const int*   __restrict__ tl,
                                             const float* __restrict__ Wmat,
                                             const float* __restrict__ bias,
                                             float*       __restrict__ out) {
    __shared__ float wdl[ENC];
    __shared__ float wdr[ENC];
    __shared__ float sdl[TMAX];
    __shared__ float sdr[TMAX];
    __shared__ float wsum[8];
    __shared__ int   s_ticket;

    const int tid  = threadIdx.x;
    const int warp = tid >> 5;
    const int lane = tid & 31;
    const int row  = blockIdx.x * 8 + warp;  // 0..2047 == b*64 + t
    const int b    = blockIdx.x >> 3;

    // Stage weight-difference vectors once per CTA.
    for (int i = tid; i < ENC; i += 256) {
        wdl[i] = Wmat[1024 + i] - Wmat[i];         // Wl1 - Wl0
        wdr[i] = Wmat[1536 + i] - Wmat[512 + i];   // Wr1 - Wr0
    }
    __syncthreads();

    // Gather row and compute the two weight-difference dot products.
    const int id = ids[row];
    const float4* __restrict__ src = (const float4*)(enc + ((size_t)(row >> 6) * SEQ + id) * ENC);
    const float4* __restrict__ l4  = (const float4*)wdl;
    const float4* __restrict__ r4  = (const float4*)wdr;

    float dl = 0.f, dr = 0.f;
#pragma unroll
    for (int i = 0; i < 4; i++) {
        const int c = lane + i * 32;               // 128 float4 per row
        const float4 x  = src[c];
        const float4 a  = l4[c];
        const float4 bb = r4[c];
        dl = fmaf(x.x, a.x,  fmaf(x.y, a.y,  fmaf(x.z, a.z,  fmaf(x.w, a.w,  dl))));
        dr = fmaf(x.x, bb.x, fmaf(x.y, bb.y, fmaf(x.z, bb.z, fmaf(x.w, bb.w, dr))));
    }
#pragma unroll
    for (int o = 16; o; o >>= 1) {
        dl += __shfl_xor_sync(0xffffffffu, dl, o);
        dr += __shfl_xor_sync(0xffffffffu, dr, o);
    }
    if (lane == 0) {
        g_dl[row] = dl;
        g_dr[row] = dr;
    }
    __syncthreads();

    // ---- Per-batch software barrier: last of the 8 CTAs becomes consumer ----
    if (tid == 0) {
        __threadfence();                            // release (cumulative w/ bar.sync)
        s_ticket = atomicAdd(&g_barr[b], 1);
    }
    __syncthreads();
    if (s_ticket != 7) return;                      // not the last CTA of this batch

    if (tid == 0) {
        g_barr[b] = 0;                              // reset for next replay
        __threadfence();                            // acquire (cumulative)
    }
    __syncthreads();

    // ---- Phase 2: this CTA computes batch b's pairwise CE ----
    if (tid < TMAX) {
        sdl[tid] = __ldcg(&g_dl[b * TMAX + tid]);   // bypass incoherent L1
        sdr[tid] = __ldcg(&g_dr[b * TMAX + tid]);
    }
    __syncthreads();

    const int   T  = tl[b];
    const float db = bias[1] - bias[0];

    float sum = 0.f;
    // 64x64 = 4096 pairs, 16 per thread; valid: k < j < T.
    // Uses softplus(-d) = softplus(d) - d to avoid the label select.
#pragma unroll 4
    for (int p = tid; p < TMAX * TMAX; p += 256) {
        const int j = p >> 6;
        const int k = p & 63;
        if (k < j && j < T) {
            const float d  = sdl[j] + sdr[k] + db;
            float sp = fmaxf(d, 0.f) + __logf(1.f + __expf(-fabsf(d)));
            if (k == j - 1) sp -= d;
            sum += sp;
        }
    }

#pragma unroll
    for (int o = 16; o; o >>= 1) sum += __shfl_xor_sync(0xffffffffu, sum, o);
    if (lane == 0) wsum[warp] = sum;
    __syncthreads();

    if (tid == 0) {
        float s = wsum[0];
#pragma unroll
        for (int w = 1; w < 8; w++) s += wsum[w];
        atomicAdd(&g_sum, s);
        atomicAdd(&g_cnt, T * (T - 1) / 2);
        __threadfence();
        const unsigned ticket = atomicAdd(&g_done, 1u);
        if (ticket == BSZ - 1) {
            const float total = atomicAdd(&g_sum, 0.f);   // coherent L2 read
            const int   cnt   = atomicAdd(&g_cnt, 0);
            out[0] = total / (float)(cnt < 1 ? 1 : cnt);
            // Reset for next graph replay.
            g_sum  = 0.f;
            g_cnt  = 0;
            g_done = 0u;
        }
    }
}

extern "C" void kernel_launch(void* const* d_in, const int* in_sizes, int n_in,
                              void* d_out, int out_size) {
    // metadata order: encoder_output, his_turn_end_ids, turn_lengths, W, b
    const float* enc  = (const float*)d_in[0];
    const int*   ids  = (const int*)  d_in[1];
    const int*   tl   = (const int*)  d_in[2];
    const float* W    = (const float*)d_in[3];
    const float* bias = (const float*)d_in[4];
    float*       out  = (float*)d_out;

    fused<<<256, 256>>>(enc, ids, tl, W, bias, out);
}

// round 15
// speedup vs baseline: 3.5143x; 1.1964x over previous
#include <cuda_runtime.h>
#include <math.h>

#define BSZ  32
#define SEQ  4096
#define ENC  512
#define TMAX 64

// Cross-batch reduction scratch (__device__ globals — allocation-guard safe).
// Reset by the last-finishing CTA each launch => graph replays deterministic.
__device__ float    g_sum;
__device__ int      g_cnt;
__device__ unsigned g_done;

// One CTA per batch element. 32 warps; warp w owns rows 2w and 2w+1.
// Phase 1: stage weight-diff vectors in smem (independent of the gather, so
//          its DRAM latency overlaps the ids->x dependent-load chain).
// Phase 2: gather the two rows, dual dot products vs smem weight diffs,
//          warp-reduce, stash dl/dr in smem.
// Phase 3: after one __syncthreads, 4096 (j,k) pairs across 1024 threads,
//          block-reduce, one atomicAdd + done-ticket.
__global__ void __launch_bounds__(1024, 1)
fused(const float* __restrict__ enc,
      const int*   __restrict__ ids,
      const int*   __restrict__ tl,
      const float* __restrict__ Wmat,
      const float* __restrict__ bias,
      float*       __restrict__ out) {
    __shared__ float wdl[ENC];        // Wl1 - Wl0
    __shared__ float wdr[ENC];        // Wr1 - Wr0
    __shared__ float sdl[TMAX];
    __shared__ float sdr[TMAX];
    __shared__ float wsum[32];

    const int b    = blockIdx.x;
    const int tid  = threadIdx.x;
    const int warp = tid >> 5;
    const int lane = tid & 31;

    // ---- Issue ids loads first (head of the dependent chain) ----
    const int r0  = 2 * warp;                      // local rows of this warp
    const int id0 = ids[b * TMAX + r0];
    const int id1 = ids[b * TMAX + r0 + 1];

    // ---- Stage weight-difference vectors (independent loads, overlap) ----
    // W layout (2, 2*ENC) row-major: W0 = W[0..1024), W1 = W[1024..2048).
    if (tid < ENC) {
        wdl[tid] = Wmat[1024 + tid] - Wmat[tid];
    } else {
        const int i = tid - ENC;                   // 0..511
        wdr[i] = Wmat[1536 + i] - Wmat[512 + i];
    }

    // ---- Gather both rows into registers (x loads depend only on ids) ----
    const float4* __restrict__ src0 =
        (const float4*)(enc + ((size_t)b * SEQ + id0) * ENC);
    const float4* __restrict__ src1 =
        (const float4*)(enc + ((size_t)b * SEQ + id1) * ENC);

    float4 x0[4], x1[4];
#pragma unroll
    for (int i = 0; i < 4; i++) {
        const int c = lane + i * 32;               // 128 float4 per row
        x0[i] = src0[c];
        x1[i] = src1[c];
    }

    __syncthreads();                               // wdl/wdr staged

    const float4* __restrict__ l4 = (const float4*)wdl;
    const float4* __restrict__ r4 = (const float4*)wdr;

    float dl0 = 0.f, dr0 = 0.f, dl1 = 0.f, dr1 = 0.f;
#pragma unroll
    for (int i = 0; i < 4; i++) {
        const int c = lane + i * 32;
        const float4 a  = l4[c];
        const float4 bb = r4[c];
        dl0 = fmaf(x0[i].x, a.x,  fmaf(x0[i].y, a.y,  fmaf(x0[i].z, a.z,  fmaf(x0[i].w, a.w,  dl0))));
        dr0 = fmaf(x0[i].x, bb.x, fmaf(x0[i].y, bb.y, fmaf(x0[i].z, bb.z, fmaf(x0[i].w, bb.w, dr0))));
        dl1 = fmaf(x1[i].x, a.x,  fmaf(x1[i].y, a.y,  fmaf(x1[i].z, a.z,  fmaf(x1[i].w, a.w,  dl1))));
        dr1 = fmaf(x1[i].x, bb.x, fmaf(x1[i].y, bb.y, fmaf(x1[i].z, bb.z, fmaf(x1[i].w, bb.w, dr1))));
    }
#pragma unroll
    for (int o = 16; o; o >>= 1) {
        dl0 += __shfl_xor_sync(0xffffffffu, dl0, o);
        dr0 += __shfl_xor_sync(0xffffffffu, dr0, o);
        dl1 += __shfl_xor_sync(0xffffffffu, dl1, o);
        dr1 += __shfl_xor_sync(0xffffffffu, dr1, o);
    }
    if (lane == 0) {
        sdl[r0]     = dl0;
        sdr[r0]     = dr0;
        sdl[r0 + 1] = dl1;
        sdr[r0 + 1] = dr1;
    }
    __syncthreads();

    // ---- Phase 3: pairwise CE for this batch ----
    const int   T  = tl[b];
    const float db = bias[1] - bias[0];

    float sum = 0.f;
    // 64*64 = 4096 pairs, exactly 4 per thread; valid: k < j < T.
    // softplus(-d) = softplus(d) - d kills the label select.
#pragma unroll
    for (int u = 0; u < 4; u++) {
        const int p = tid + u * 1024;
        const int j = p >> 6;
        const int k = p & 63;
        if (k < j && j < T) {
            const float d  = sdl[j] + sdr[k] + db;
            float sp = fmaxf(d, 0.f) + __logf(1.f + __expf(-fabsf(d)));
            if (k == j - 1) sp -= d;
            sum += sp;
        }
    }

#pragma unroll
    for (int o = 16; o; o >>= 1) sum += __shfl_xor_sync(0xffffffffu, sum, o);
    if (lane == 0) wsum[warp] = sum;
    __syncthreads();

    if (warp == 0) {
        sum = wsum[lane];
#pragma unroll
        for (int o = 16; o; o >>= 1) sum += __shfl_xor_sync(0xffffffffu, sum, o);

        if (lane == 0) {
            atomicAdd(&g_sum, sum);
            atomicAdd(&g_cnt, T * (T - 1) / 2);
            __threadfence();
            const unsigned ticket = atomicAdd(&g_done, 1u);
            if (ticket == BSZ - 1) {
                const float total = atomicAdd(&g_sum, 0.f);   // coherent L2 read
                const int   cnt   = atomicAdd(&g_cnt, 0);
                out[0] = total / (float)(cnt < 1 ? 1 : cnt);
                // Reset for the next graph replay.
                g_sum  = 0.f;
                g_cnt  = 0;
                g_done = 0u;
            }
        }
    }
}

extern "C" void kernel_launch(void* const* d_in, const int* in_sizes, int n_in,
                              void* d_out, int out_size) {
    // metadata order: encoder_output, his_turn_end_ids, turn_lengths, W, b
    const float* enc  = (const float*)d_in[0];
    const int*   ids  = (const int*)  d_in[1];
    const int*   tl   = (const int*)  d_in[2];
    const float* W    = (const float*)d_in[3];
    const float* bias = (const float*)d_in[4];
    float*       out  = (float*)d_out;

    fused<<<BSZ, 1024>>>(enc, ids, tl, W, bias, out);
}